// round 11
// baseline (speedup 1.0000x reference)
#include <cuda_runtime.h>
#include <cuda_fp16.h>
#include <math.h>
#include <stdint.h>

#define BB    8
#define TT    4096
#define NROWS (BB*TT)      // 32768
#define DD    1024
#define NSC   512
#define PFD   1024
#define HID   128

// internal activations in fp16
__device__ __half g_h1[(size_t)NROWS * HID];
__device__ __half g_h2[(size_t)NROWS * HID];
__device__ __half g_err16[(size_t)NROWS * DD];    // masked err fp16 (GEMM3 input)
__device__ __half g_delta16[(size_t)NROWS * NSC]; // delta fp16 (scan input)
__device__ float  g_err[(size_t)NROWS * DD];      // fallback err dst if out small

// fp16 weight copies
__device__ __half g_fw1h[PFD * HID];
__device__ __half g_fw2h[HID * DD];
__device__ __half g_ew1h[DD * HID];
__device__ __half g_ew2h[HID * NSC];

__device__ __forceinline__ float gelu_f(float x) {
    return 0.5f * x * (1.0f + erff(x * 0.7071067811865476f));
}

__device__ __forceinline__ void cp_async16(uint32_t s, const void* g) {
    asm volatile("cp.async.cg.shared.global [%0], [%1], 16;" :: "r"(s), "l"(g));
}
__device__ __forceinline__ void cp_commit() {
    asm volatile("cp.async.commit_group;");
}
template<int N>
__device__ __forceinline__ void cp_wait() {
    asm volatile("cp.async.wait_group %0;" :: "n"(N));
}

__device__ __forceinline__ void ldm_x4(uint32_t* r, uint32_t addr) {
    asm volatile("ldmatrix.sync.aligned.m8n8.x4.shared.b16 {%0,%1,%2,%3}, [%4];"
                 : "=r"(r[0]), "=r"(r[1]), "=r"(r[2]), "=r"(r[3]) : "r"(addr));
}
__device__ __forceinline__ void ldm_x4_t(uint32_t* r, uint32_t addr) {
    asm volatile("ldmatrix.sync.aligned.m8n8.x4.trans.shared.b16 {%0,%1,%2,%3}, [%4];"
                 : "=r"(r[0]), "=r"(r[1]), "=r"(r[2]), "=r"(r[3]) : "r"(addr));
}
__device__ __forceinline__ void mma_f16(float* c,
    uint32_t a0, uint32_t a1, uint32_t a2, uint32_t a3,
    uint32_t b0, uint32_t b1)
{
    asm volatile(
        "mma.sync.aligned.m16n8k16.row.col.f32.f16.f16.f32 "
        "{%0,%1,%2,%3}, {%4,%5,%6,%7}, {%8,%9}, {%0,%1,%2,%3};"
        : "+f"(c[0]), "+f"(c[1]), "+f"(c[2]), "+f"(c[3])
        : "r"(a0), "r"(a1), "r"(a2), "r"(a3), "r"(b0), "r"(b1));
}

// ---------------------------------------------------------------------------
// fp16 tensor GEMM (mma.sync m16n8k16 + ldmatrix), 2-stage cp.async, BK=64.
// C[NROWS, NC] = epi( A[NROWS,K] @ W[K,NC] + bias ),  fp32 accumulate.
// MODE 1: A = posfeat(theta) (trig reg path); epi = gelu      -> g_h1 (h16)
// MODE 2: A = g_h1 (async); epi = content-(acc+b) -> err f32 + masked fp16
//         (fp16 tile staged in SMEM, then fully-coalesced store -> g_err16)
// MODE 3: A = g_err16 (async); epi = gelu                     -> g_h2 (h16)
// MODE 4: A = g_h2 (async); epi = acc+b, SMEM-staged fp16     -> g_delta16
// Block 128x128, 8 warps (2m x 4n), warp tile 64x32.
// A [128][72]h (144B), B [64][136]h (272B): conflict-free ldmatrix.
// ---------------------------------------------------------------------------
template<int MODE>
__global__ __launch_bounds__(256, 2)
void gemm_h(const float* __restrict__ Af,        // theta (M1)
            const __half* __restrict__ Wh,
            const float* __restrict__ bias,
            const float* __restrict__ content,
            const unsigned int* __restrict__ mask,
            float* __restrict__ outp,            // M2 err dst
            int K, int NC)
{
    constexpr int BK = 64;
    constexpr int AS_STR = 72;                   // halves (144 B)
    constexpr int BS_STR = 136;                  // halves (272 B)
    constexpr int A_STG = 128 * AS_STR * 2;      // 18432 B
    constexpr int B_STG = BK * BS_STR * 2;       // 17408 B
    constexpr bool AASYNC = (MODE != 1);

    extern __shared__ __align__(16) char smem[];
    const uint32_t sbA = (uint32_t)__cvta_generic_to_shared(smem);
    const uint32_t sbB = sbA + 2 * A_STG;

    const int tid  = threadIdx.x;
    const int lane = tid & 31;
    const int warp = tid >> 5;
    const int wm = warp >> 2;        // 0..1
    const int wn = warp & 3;         // 0..3
    const int lr = lane >> 2;        // 0..7
    const int lc = lane & 3;         // 0..3
    const int row0 = blockIdx.y * 128;
    const int col0 = blockIdx.x * 128;

    const __half* Ah;                             // async A source
    if      (MODE == 2) Ah = g_h1;
    else if (MODE == 3) Ah = g_err16;
    else                Ah = g_h2;                // MODE 4
    const float* Afp = Af;                        // MODE 1: theta

    const int NIT = K / BK;

    float apre[2][8];                             // MODE 1 staging

    auto issue_B = [&](int t, int s) {
        int k0 = t * BK;
        #pragma unroll
        for (int i = 0; i < 4; i++) {
            int e  = tid + i * 256;      // 0..1023
            int k  = e >> 4;             // 0..63
            int nc = e & 15;             // 8-half chunk
            uint32_t d = sbB + s * B_STG + (uint32_t)(k * BS_STR + nc * 8) * 2u;
            cp_async16(d, Wh + (size_t)(k0 + k) * NC + col0 + nc * 8);
        }
    };
    auto issue_A = [&](int t, int s) {   // async modes (half source, row stride K)
        int k0 = t * BK;
        #pragma unroll
        for (int i = 0; i < 4; i++) {
            int e  = tid + i * 256;      // 0..1023
            int m  = e >> 3;             // 0..127
            int ch = e & 7;              // 8-half chunk (64 halves/row)
            uint32_t d = sbA + s * A_STG + (uint32_t)(m * AS_STR + ch * 8) * 2u;
            cp_async16(d, Ah + (size_t)(row0 + m) * K + k0 + ch * 8);
        }
    };
    // MODE 1 reg path: 32-col sub-tiles (sub = 0/1 within the BK=64 tile)
    auto ldg_A = [&](int t, int sub) {
        #pragma unroll
        for (int i = 0; i < 2; i++) {
            int e  = tid + i * 256;
            int m  = e >> 2;             // 0..127
            int ch = e & 3;              // 8-float chunk
            int kk = t * BK + sub * 32 + ch * 8;
            int row = row0 + m;
            int h = kk >> 6;
            int j = kk & 63;
            const float* p = &Afp[(size_t)row * 512 + (h << 5) + (j & 31)];
            float4 u0 = *reinterpret_cast<const float4*>(p);
            float4 u1 = *reinterpret_cast<const float4*>(p + 4);
            apre[i][0]=u0.x; apre[i][1]=u0.y; apre[i][2]=u0.z; apre[i][3]=u0.w;
            apre[i][4]=u1.x; apre[i][5]=u1.y; apre[i][6]=u1.z; apre[i][7]=u1.w;
        }
    };
    auto sts_A = [&](int t, int sub, int s) {
        #pragma unroll
        for (int i = 0; i < 2; i++) {
            int e  = tid + i * 256;
            int m  = e >> 2;
            int ch = e & 3;
            int kk = t * BK + sub * 32 + ch * 8;
            bool use_cos = (kk & 63) < 32;
            float v[8];
            #pragma unroll
            for (int q = 0; q < 8; q++)
                v[q] = use_cos ? __cosf(apre[i][q]) : __sinf(apre[i][q]);
            union { __half2 h2[4]; uint4 u; } pk;
            pk.h2[0] = __floats2half2_rn(v[0], v[1]);
            pk.h2[1] = __floats2half2_rn(v[2], v[3]);
            pk.h2[2] = __floats2half2_rn(v[4], v[5]);
            pk.h2[3] = __floats2half2_rn(v[6], v[7]);
            *reinterpret_cast<uint4*>(smem + (size_t)s * A_STG
                                      + (m * AS_STR + sub * 32 + ch * 8) * 2) = pk.u;
        }
    };

    float acc[4][4][4];
    #pragma unroll
    for (int mt = 0; mt < 4; mt++)
        #pragma unroll
        for (int nt = 0; nt < 4; nt++)
            #pragma unroll
            for (int c = 0; c < 4; c++) acc[mt][nt][c] = 0.0f;

    const int a_row = wm * 64 + (lane & 15);
    const int a_col = (lane >> 4) << 3;
    const int b_row = lane & 15;
    const int b_col = wn * 32 + ((lane >> 4) << 3);

    // ---- prologue ----
    issue_B(0, 0);
    if (AASYNC) issue_A(0, 0);
    cp_commit();
    if (!AASYNC) { ldg_A(0, 0); sts_A(0, 0, 0); ldg_A(0, 1); sts_A(0, 1, 0); }

    // ---- main loop (2-stage) ----
    for (int it = 0; it < NIT; it++) {
        const int cur = it & 1, nxt = cur ^ 1;
        const bool more = (it + 1 < NIT);

        if (more) {
            issue_B(it + 1, nxt);
            if (AASYNC) issue_A(it + 1, nxt);
            cp_commit();
            if (!AASYNC) ldg_A(it + 1, 0);
        }
        if (more) cp_wait<1>(); else cp_wait<0>();
        __syncthreads();

        const uint32_t aS = sbA + cur * A_STG;
        const uint32_t bS = sbB + cur * B_STG;
        #pragma unroll
        for (int ks = 0; ks < 4; ks++) {
            uint32_t af[4][4], bf[2][4];
            #pragma unroll
            for (int mt = 0; mt < 4; mt++)
                ldm_x4(af[mt], aS + (uint32_t)((a_row + mt * 16) * AS_STR
                                               + ks * 16 + a_col) * 2u);
            #pragma unroll
            for (int np = 0; np < 2; np++)
                ldm_x4_t(bf[np], bS + (uint32_t)((ks * 16 + b_row) * BS_STR
                                                 + b_col + np * 16) * 2u);
            #pragma unroll
            for (int mt = 0; mt < 4; mt++)
                #pragma unroll
                for (int nt = 0; nt < 4; nt++)
                    mma_f16(acc[mt][nt],
                            af[mt][0], af[mt][1], af[mt][2], af[mt][3],
                            bf[nt >> 1][(nt & 1) * 2], bf[nt >> 1][(nt & 1) * 2 + 1]);

            if (!AASYNC && more && ks == 1) {
                sts_A(it + 1, 0, nxt);
                ldg_A(it + 1, 1);
            }
        }
        if (!AASYNC && more) sts_A(it + 1, 1, nxt);
        __syncthreads();
    }

    // ---- epilogue ----
    // MODE 2/4: stage fp16 tile in SMEM (pipeline smem free after final barrier),
    // then fully-coalesced 16B global stores (avoids write-allocate scatter).
    __half* es = reinterpret_cast<__half*>(smem);
    constexpr int ES_STR = 136;   // halves; 128x136x2 = 34816 B <= 71680

    #pragma unroll
    for (int mt = 0; mt < 4; mt++) {
        #pragma unroll
        for (int nt = 0; nt < 4; nt++) {
            int rl0 = wm * 64 + mt * 16 + lr;
            int cbl = wn * 32 + nt * 8 + lc * 2;
            int cb  = col0 + cbl;
            float b0 = bias[cb], b1 = bias[cb + 1];
            #pragma unroll
            for (int hf = 0; hf < 2; hf++) {
                int rl = rl0 + hf * 8;
                int r  = row0 + rl;
                float vx = acc[mt][nt][hf * 2 + 0] + b0;
                float vy = acc[mt][nt][hf * 2 + 1] + b1;
                if (MODE == 1 || MODE == 3) {
                    vx = gelu_f(vx); vy = gelu_f(vy);
                    __half* dst = (MODE == 1) ? g_h1 : g_h2;
                    *reinterpret_cast<__half2*>(&dst[(size_t)r * NC + cbl])
                        = __floats2half2_rn(vx, vy);
                } else if (MODE == 2) {
                    float* dst = (outp != nullptr) ? outp : g_err;
                    float2 cv = *reinterpret_cast<const float2*>(
                        &content[(size_t)r * DD + cb]);
                    float2 v; v.x = cv.x - vx; v.y = cv.y - vy;
                    *reinterpret_cast<float2*>(&dst[(size_t)r * NC + cb]) = v;
                    *reinterpret_cast<__half2*>(&es[rl * ES_STR + cbl])
                        = __floats2half2_rn(v.x, v.y);
                } else {  // MODE 4
                    *reinterpret_cast<__half2*>(&es[rl * ES_STR + cbl])
                        = __floats2half2_rn(vx, vy);
                }
            }
        }
    }

    if (MODE == 2 || MODE == 4) {
        __syncthreads();
        const int rl    = tid >> 1;          // 0..127
        const int cpart = (tid & 1) * 64;    // 0 / 64
        const int row   = row0 + rl;
        bool zero = false;
        if (MODE == 2) zero = (mask[row] == 0u);
        __half* dst16 = (MODE == 2) ? g_err16 : g_delta16;
        #pragma unroll
        for (int q = 0; q < 8; q++) {
            uint4 u = *reinterpret_cast<const uint4*>(&es[rl * ES_STR + cpart + q * 8]);
            if (MODE == 2 && zero) u = make_uint4(0u, 0u, 0u, 0u);
            *reinterpret_cast<uint4*>(&dst16[(size_t)row * NC + col0 + cpart + q * 8]) = u;
        }
    }
}

// ---------------------------------------------------------------------------
// One fused conversion kernel: all 4 weights fp32->fp16 + gate output.
// ---------------------------------------------------------------------------
__global__ void cvt_all_k(const float* __restrict__ fw1, const float* __restrict__ fw2,
                          const float* __restrict__ ew1, const float* __restrict__ ew2,
                          __half* __restrict__ dw1, __half* __restrict__ dw2,
                          __half* __restrict__ dw3, __half* __restrict__ dw4,
                          const float* __restrict__ log_gain, float* gate_dst)
{
    const int n1 = PFD * HID / 2, n2 = HID * DD / 2, n3 = DD * HID / 2, n4 = HID * NSC / 2;
    const int total = n1 + n2 + n3 + n4;
    int i0 = blockIdx.x * blockDim.x + threadIdx.x;
    for (int j = i0; j < total; j += gridDim.x * blockDim.x) {
        const float2* s; __half2* d; int k = j;
        if (k < n1)              { s = (const float2*)fw1; d = (__half2*)dw1; }
        else if ((k -= n1) < n2) { s = (const float2*)fw2; d = (__half2*)dw2; }
        else if ((k -= n2) < n3) { s = (const float2*)ew1; d = (__half2*)dw3; }
        else { k -= n3;            s = (const float2*)ew2; d = (__half2*)dw4; }
        float2 v = s[k];
        d[k] = __floats2half2_rn(v.x, v.y);
    }
    if (gate_dst != nullptr && i0 < NSC)
        gate_dst[i0] = 1.0f / (1.0f + expf(-log_gain[i0]));
}

// ---------------------------------------------------------------------------
// Chunked affine scan over fp16 delta; g^64 underflow -> 64-step halo exact.
// ---------------------------------------------------------------------------
__global__ __launch_bounds__(512)
void scan_k(const float* __restrict__ theta,
            const float* __restrict__ log_gain,
            float* __restrict__ theta_hat)
{
    const int c = threadIdx.x;
    const int b = blockIdx.x;
    const int chunk = blockIdx.y;
    const float g = 1.0f / (1.0f + expf(-log_gain[c]));

    const int t0 = chunk * 128;
    const int ts = (t0 >= 64) ? (t0 - 64) : 0;
    const size_t base = ((size_t)b * TT) * NSC + c;

    float d = 0.0f;
    for (int t = ts; t < t0; t++)
        d = fmaf(g, d, __half2float(g_delta16[base + (size_t)t * NSC]));
    for (int t = t0; t < t0 + 128; t++) {
        size_t idx = base + (size_t)t * NSC;
        d = fmaf(g, d, __half2float(g_delta16[idx]));
        theta_hat[idx] = theta[idx] + d;
    }
}

// ---------------------------------------------------------------------------
extern "C" void kernel_launch(void* const* d_in, const int* in_sizes, int n_in,
                              void* d_out, int out_size)
{
    const float* theta    = (const float*)d_in[0];
    const float* content  = (const float*)d_in[1];
    const unsigned int* mask = (const unsigned int*)d_in[2];
    const float* fw1 = (const float*)d_in[3];
    const float* fb1 = (const float*)d_in[4];
    const float* fw2 = (const float*)d_in[5];
    const float* fb2 = (const float*)d_in[6];
    const float* ew1 = (const float*)d_in[7];
    const float* eb1 = (const float*)d_in[8];
    const float* ew2 = (const float*)d_in[9];
    const float* eb2 = (const float*)d_in[10];
    const float* log_gain = (const float*)d_in[11];

    float* out = (float*)d_out;
    const size_t sz_theta = (size_t)NROWS * NSC;
    const size_t sz_err   = (size_t)NROWS * DD;
    const size_t need_full = sz_theta + sz_err + NSC;

    float* theta_hat = out;
    bool full = ((size_t)out_size >= need_full);
    float* err_dst  = full ? (out + sz_theta) : nullptr;
    float* gate_dst = full ? (out + sz_theta + sz_err) : nullptr;

    // resolve device scratch symbol addresses (host side) — REQUIRED
    __half *p_fw1h, *p_fw2h, *p_ew1h, *p_ew2h;
    cudaGetSymbolAddress((void**)&p_fw1h, g_fw1h);
    cudaGetSymbolAddress((void**)&p_fw2h, g_fw2h);
    cudaGetSymbolAddress((void**)&p_ew1h, g_ew1h);
    cudaGetSymbolAddress((void**)&p_ew2h, g_ew2h);

    // fused weight conversion + gate
    cvt_all_k<<<224, 256>>>(fw1, fw2, ew1, ew2,
                            p_fw1h, p_fw2h, p_ew1h, p_ew2h, log_gain, gate_dst);

    const int SMEM_BYTES = 2 * (128 * 72 * 2) + 2 * (64 * 136 * 2);  // 71680

    cudaFuncSetAttribute(gemm_h<1>, cudaFuncAttributeMaxDynamicSharedMemorySize, SMEM_BYTES);
    cudaFuncSetAttribute(gemm_h<2>, cudaFuncAttributeMaxDynamicSharedMemorySize, SMEM_BYTES);
    cudaFuncSetAttribute(gemm_h<3>, cudaFuncAttributeMaxDynamicSharedMemorySize, SMEM_BYTES);
    cudaFuncSetAttribute(gemm_h<4>, cudaFuncAttributeMaxDynamicSharedMemorySize, SMEM_BYTES);

    // GEMM1: h1 = gelu(posfeat(theta) @ fw1 + fb1)   [32768x128, K=1024]
    gemm_h<1><<<dim3(1, NROWS / 128), 256, SMEM_BYTES>>>(theta, p_fw1h, fb1, nullptr, nullptr, nullptr, PFD, HID);
    // GEMM2: err = content - (h1 @ fw2 + fb2) -> f32 out + masked fp16 g_err16
    gemm_h<2><<<dim3(DD / 128, NROWS / 128), 256, SMEM_BYTES>>>(nullptr, p_fw2h, fb2, content, mask, err_dst, HID, DD);
    // GEMM3: h2 = gelu(g_err16 @ ew1 + eb1)          [32768x128, K=1024]
    gemm_h<3><<<dim3(1, NROWS / 128), 256, SMEM_BYTES>>>(nullptr, p_ew1h, eb1, nullptr, nullptr, nullptr, DD, HID);
    // GEMM4: delta = h2 @ ew2 + eb2 -> fp16 g_delta16 [32768x512, K=128]
    gemm_h<4><<<dim3(NSC / 128, NROWS / 128), 256, SMEM_BYTES>>>(nullptr, p_ew2h, eb2, nullptr, nullptr, nullptr, HID, NSC);
    // Scan + theta_hat
    scan_k<<<dim3(BB, TT / 128), 512>>>(theta, log_gain, theta_hat);
}